// round 11
// baseline (speedup 1.0000x reference)
#include <cuda_runtime.h>
#include <cstdint>

#define B_    16
#define N_    512
#define INF_  256
#define OUTF_ 256
#define H_    8
#define NET_  50
#define LOG2E 1.4426950408889634f
#define IT_   32      // i-rows per block (attn)
#define CJ_   32      // j-chunk (attn)
#define WSTR  264     // WhS row stride (u32)
#define WBUF  (CJ_ * WSTR)   // 8448

// SMEM offsets (float units)
#define OFF_S2    0
#define OFF_EMB   4096
#define OFF_G     4608
#define OFF_B     4864
#define OFF_S1    5120
#define OFF_DEN   5376
#define OFF_CODES 5632              // 2 x 384 u32 (32 rows x 12-padded, 16B-aligned)
#define OFF_ADJ   6400              // 2 x 256 uint4 = 2048 u32
#define OFF_ET    8448              // 2048 u32
#define OFF_WH    10496             // 2 x 8448 u32
#define SMEM_FLOATS (OFF_WH + 2 * WBUF)   // 27392 -> 109568 B

// Scratch (allocation-free rule: __device__ globals)
// g_Wh: row-major [row][256]; within each head's 32 dims permuted:
// storage pos p = g*4 + nf  <->  dim dl = nf*8 + g.
__device__ float g_Wh[B_ * N_ * OUTF_];
__device__ float g_s1[B_ * N_ * H_];      // pre-scaled by log2e
__device__ float g_s2[B_ * N_ * H_];

// ---------------------------------------------------------------------------
__device__ __forceinline__ float ex2f(float x) {   // MUFU.EX2
    float r;
    asm("ex2.approx.f32 %0, %1;" : "=f"(r) : "f"(x));
    return r;
}
__device__ __forceinline__ float tf32f(float f) {
    unsigned int u;
    asm("cvt.rna.tf32.f32 %0, %1;" : "=r"(u) : "f"(f));
    return __uint_as_float(u);
}
__device__ __forceinline__ void mma_tf32(float acc[4], float a0, float a1f,
                                         float a2f, float a3f, float b0, float b1) {
    asm volatile(
        "mma.sync.aligned.m16n8k8.row.col.f32.tf32.tf32.f32 "
        "{%0,%1,%2,%3}, {%4,%5,%6,%7}, {%8,%9}, {%0,%1,%2,%3};"
        : "+f"(acc[0]), "+f"(acc[1]), "+f"(acc[2]), "+f"(acc[3])
        : "r"(__float_as_uint(a0)), "r"(__float_as_uint(a1f)),
          "r"(__float_as_uint(a2f)), "r"(__float_as_uint(a3f)),
          "r"(__float_as_uint(b0)), "r"(__float_as_uint(b1)));
}
__device__ __forceinline__ void cp_async16(unsigned int smem_addr, const void* gptr) {
    asm volatile("cp.async.cg.shared.global [%0], [%1], 16;" ::"r"(smem_addr), "l"(gptr));
}
__device__ __forceinline__ unsigned int smem_u32(const void* p) {
    unsigned int a;
    asm("{ .reg .u64 t; cvta.to.shared.u64 t, %1; cvt.u32.u64 %0, t; }" : "=r"(a) : "l"(p));
    return a;
}

// ---------------------------------------------------------------------------
// K1: Wh = x @ W via 2xTF32-split tensor-core GEMM + fused s1/s2 epilogue.
// M-tile 64 (grid 256 blocks -> all SMs busy), N-tile 128, k-chunk 16.
// 8 warps: wm=warp>>1 (M16 tile), wn=warp&1 (N64 half).
// ---------------------------------------------------------------------------
#define ASTR 20
#define BSTR 136
__global__ __launch_bounds__(256, 2) void gemm_score_kernel(
    const float* __restrict__ A, const float* __restrict__ Bw,
    const float* __restrict__ a1, const float* __restrict__ a2) {
    __shared__ float Ahi[64 * ASTR], Alo[64 * ASTR];
    __shared__ float Bs[16 * BSTR];
    __shared__ float a1s[32], a2s[32];

    const int tid = threadIdx.x;
    const int m0 = blockIdx.y * 64;
    const int n0 = blockIdx.x * 128;
    if (tid < 32) { a1s[tid] = a1[tid]; a2s[tid] = a2[tid]; }

    const int warp = tid >> 5, lane = tid & 31;
    const int wm = warp >> 1, wn = warp & 1;
    const int g = lane >> 2, t = lane & 3;

    float acc[8][4];
#pragma unroll
    for (int nf = 0; nf < 8; nf++)
#pragma unroll
        for (int c = 0; c < 4; c++) acc[nf][c] = 0.f;

    float4 va, vb[2];
    va = ((const float4*)A)[(size_t)(m0 + (tid >> 2)) * 64 + (tid & 3)];
#pragma unroll
    for (int it = 0; it < 2; it++) {
        int idx = tid + it * 256;
        vb[it] = ((const float4*)Bw)[(size_t)(idx >> 5) * 64 + (n0 >> 2) + (idx & 31)];
    }

    for (int k0 = 0; k0 < INF_; k0 += 16) {
        __syncthreads();   // previous chunk's smem readers done
        {
            float4 v = va;
            float4 hi, lo;
            hi.x = tf32f(v.x); lo.x = tf32f(v.x - hi.x);
            hi.y = tf32f(v.y); lo.y = tf32f(v.y - hi.y);
            hi.z = tf32f(v.z); lo.z = tf32f(v.z - hi.z);
            hi.w = tf32f(v.w); lo.w = tf32f(v.w - hi.w);
            int off = (tid >> 2) * ASTR + (tid & 3) * 4;
            *(float4*)&Ahi[off] = hi;
            *(float4*)&Alo[off] = lo;
        }
#pragma unroll
        for (int it = 0; it < 2; it++) {
            int idx = tid + it * 256;
            float4 v = vb[it];
            float4 hi;
            hi.x = tf32f(v.x);
            hi.y = tf32f(v.y);
            hi.z = tf32f(v.z);
            hi.w = tf32f(v.w);
            *(float4*)&Bs[(idx >> 5) * BSTR + (idx & 31) * 4] = hi;
        }
        __syncthreads();
        // issue next chunk's LDGs; they complete under the MMA section
        if (k0 + 16 < INF_) {
            va = ((const float4*)A)[(size_t)(m0 + (tid >> 2)) * 64 +
                                    ((k0 + 16) >> 2) + (tid & 3)];
#pragma unroll
            for (int it = 0; it < 2; it++) {
                int idx = tid + it * 256;
                vb[it] = ((const float4*)Bw)[(size_t)(k0 + 16 + (idx >> 5)) * 64 +
                                             (n0 >> 2) + (idx & 31)];
            }
        }
#pragma unroll
        for (int k8 = 0; k8 < 2; k8++) {
            const int kk = k8 * 8 + t;
            float ah[4], al[4];
            {
                int r = (wm * 16 + g) * ASTR;
                ah[0] = Ahi[r + kk];
                ah[1] = Ahi[r + 8 * ASTR + kk];
                ah[2] = Ahi[r + kk + 4];
                ah[3] = Ahi[r + 8 * ASTR + kk + 4];
                al[0] = Alo[r + kk];
                al[1] = Alo[r + 8 * ASTR + kk];
                al[2] = Alo[r + kk + 4];
                al[3] = Alo[r + 8 * ASTR + kk + 4];
            }
#pragma unroll
            for (int nf = 0; nf < 8; nf++) {
                int c = wn * 64 + nf * 8 + g;
                float bh0 = Bs[kk * BSTR + c];
                float bh1 = Bs[(kk + 4) * BSTR + c];
                mma_tf32(acc[nf], ah[0], ah[1], ah[2], ah[3], bh0, bh1);
                mma_tf32(acc[nf], al[0], al[1], al[2], al[3], bh0, bh1);
            }
        }
    }

    // ---- epilogue: scores (fp32) + permuted tf32 Wh store ----
    const int hb = (n0 >> 5) + wn * 2;
    {
        float pA1[2] = {0.f, 0.f}, pA2[2] = {0.f, 0.f};
        float pB1[2] = {0.f, 0.f}, pB2[2] = {0.f, 0.f};
#pragma unroll
        for (int nf = 0; nf < 8; nf++) {
            int d0 = (nf * 8 + t * 2) & 31;
            int hh = nf >> 2;
            float c0 = acc[nf][0], c1 = acc[nf][1];
            float c2 = acc[nf][2], c3 = acc[nf][3];
            pA1[hh] += c0 * a1s[d0] + c1 * a1s[d0 + 1];
            pA2[hh] += c0 * a2s[d0] + c1 * a2s[d0 + 1];
            pB1[hh] += c2 * a1s[d0] + c3 * a1s[d0 + 1];
            pB2[hh] += c2 * a2s[d0] + c3 * a2s[d0 + 1];
        }
#pragma unroll
        for (int hh = 0; hh < 2; hh++) {
            pA1[hh] += __shfl_xor_sync(0xffffffffu, pA1[hh], 1);
            pA1[hh] += __shfl_xor_sync(0xffffffffu, pA1[hh], 2);
            pA2[hh] += __shfl_xor_sync(0xffffffffu, pA2[hh], 1);
            pA2[hh] += __shfl_xor_sync(0xffffffffu, pA2[hh], 2);
            pB1[hh] += __shfl_xor_sync(0xffffffffu, pB1[hh], 1);
            pB1[hh] += __shfl_xor_sync(0xffffffffu, pB1[hh], 2);
            pB2[hh] += __shfl_xor_sync(0xffffffffu, pB2[hh], 1);
            pB2[hh] += __shfl_xor_sync(0xffffffffu, pB2[hh], 2);
        }
        int rA = m0 + wm * 16 + g;
        int rB = rA + 8;
        if (t == 0) {
            g_s1[(size_t)rA * 8 + hb]     = pA1[0] * LOG2E;
            g_s1[(size_t)rA * 8 + hb + 1] = pA1[1] * LOG2E;
            g_s2[(size_t)rA * 8 + hb]     = pA2[0] * LOG2E;
            g_s2[(size_t)rA * 8 + hb + 1] = pA2[1] * LOG2E;
            g_s1[(size_t)rB * 8 + hb]     = pB1[0] * LOG2E;
            g_s1[(size_t)rB * 8 + hb + 1] = pB1[1] * LOG2E;
            g_s2[(size_t)rB * 8 + hb]     = pB2[0] * LOG2E;
            g_s2[(size_t)rB * 8 + hb + 1] = pB2[1] * LOG2E;
        }
#pragma unroll
        for (int nf = 0; nf < 8; nf++) {
            int h_idx = wn * 2 + (nf >> 2);
            int basec = n0 + h_idx * 32 + (nf & 3) + 8 * t;
            g_Wh[(size_t)rA * 256 + basec]     = tf32f(acc[nf][0]);
            g_Wh[(size_t)rA * 256 + basec + 4] = tf32f(acc[nf][1]);
            g_Wh[(size_t)rB * 256 + basec]     = tf32f(acc[nf][2]);
            g_Wh[(size_t)rB * 256 + basec + 4] = tf32f(acc[nf][3]);
        }
    }
}

// ---------------------------------------------------------------------------
// K2: fused attention, cp.async double-buffered pipeline.
// ---------------------------------------------------------------------------
__global__ void __launch_bounds__(512, 2)
attn_kernel(const int* __restrict__ adj, const int* __restrict__ et,
            const float* __restrict__ edge_emb,
            const float* __restrict__ gamma, const float* __restrict__ beta,
            float* __restrict__ out) {
    extern __shared__ float sm[];
    float* s2s  = sm + OFF_S2;
    float* embT = sm + OFF_EMB;
    float* gs   = sm + OFF_G;
    float* bs   = sm + OFF_B;
    float* s1s  = sm + OFF_S1;
    float* denS = sm + OFF_DEN;
    unsigned int* codesS = (unsigned int*)(sm + OFF_CODES);   // 2 x (32 x 12)
    uint4*        adjS   = (uint4*)(sm + OFF_ADJ);            // 2 x 256
    uint4*        etS    = (uint4*)(sm + OFF_ET);             // 2 x 256
    unsigned int* WhS    = (unsigned int*)(sm + OFF_WH);      // 2 x WBUF
    float*        outS   = (float*)(sm + OFF_WH);

    const int b     = blockIdx.y;
    const int iBase = blockIdx.x * IT_;
    const int tid   = threadIdx.x;
    const int warp  = tid >> 5, lane = tid & 31;

    const unsigned int adjU = smem_u32(adjS);
    const unsigned int etU  = smem_u32(etS);
    const unsigned int whU  = smem_u32(WhS);

    // one-time staging
    const float* s2g = g_s2 + (size_t)b * N_ * H_;
    for (int i = tid; i < N_ * H_; i += 512) s2s[i] = s2g[i];
    {
        int h = tid >> 6, e = tid & 63;
        embT[tid] = (e < NET_) ? edge_emb[e * H_ + h] * LOG2E : -12000.0f;
    }
    if (tid < 256) { gs[tid] = gamma[tid]; bs[tid] = beta[tid]; }
    if (tid < IT_ * H_) s1s[tid] = g_s1[((size_t)b * N_ + iBase) * H_ + tid];

    const int it = warp >> 3;
    const int h  = warp & 7;
    const int g  = lane >> 2;
    const int t  = lane & 3;
    const int r0 = it * 16 + g;
    const int r1 = r0 + 8;
    const unsigned int selA = 0x4440u | (unsigned int)t;
    const float* embH = embT + h * 64;

    const int4* adjRow = (const int4*)(adj + ((size_t)(b * N_ + iBase)) * N_);
    const int4* etRow  = (const int4*)(et  + ((size_t)(b * N_ + iBase)) * N_);
    const uint4* whg   = (const uint4*)(g_Wh + (size_t)b * N_ * 256);
    const int crr = tid >> 3, cww = tid & 7;   // code staging role (tid<256)

    // prologue: chunk 0 -> buffer 0
#pragma unroll
    for (int k2 = 0; k2 < 4; k2++) {
        int idx = tid + k2 * 512;
        int rr = idx >> 6, cc = idx & 63;
        cp_async16(whU + (unsigned)(rr * WSTR + cc * 4) * 4u, whg + idx);
    }
    if (tid < 256) {
        cp_async16(adjU + (unsigned)tid * 16u, adjRow + crr * (N_ / 4) + cww);
        cp_async16(etU + (unsigned)tid * 16u, etRow + crr * (N_ / 4) + cww);
    }
    asm volatile("cp.async.commit_group;");

    __syncthreads();
    const float s1a = s1s[r0 * 8 + h];
    const float s1b = s1s[r1 * 8 + h];

    float acc[4][4];
#pragma unroll
    for (int nf = 0; nf < 4; nf++)
#pragma unroll
        for (int k = 0; k < 4; k++) acc[nf][k] = 0.f;
    float den0 = 0.f, den1 = 0.f;

    for (int n = 0; n < 16; n++) {
        const int buf = n & 1;
        __syncthreads();   // sync A: compute of chunk n-1 (buffer 1-buf) drained
        if (n < 15) {
            const uint4* src = whg + (n + 1) * (CJ_ * 64);
            unsigned int dstb = whU + (unsigned)(1 - buf) * (WBUF * 4u);
#pragma unroll
            for (int k2 = 0; k2 < 4; k2++) {
                int idx = tid + k2 * 512;
                int rr = idx >> 6, cc = idx & 63;
                cp_async16(dstb + (unsigned)(rr * WSTR + cc * 4) * 4u, src + idx);
            }
            if (tid < 256) {
                unsigned int bo = (unsigned)(1 - buf) * 4096u + (unsigned)tid * 16u;
                cp_async16(adjU + bo, adjRow + crr * (N_ / 4) + (n + 1) * 8 + cww);
                cp_async16(etU + bo, etRow + crr * (N_ / 4) + (n + 1) * 8 + cww);
            }
            asm volatile("cp.async.commit_group;");
            asm volatile("cp.async.wait_group 1;");
        } else {
            asm volatile("cp.async.wait_group 0;");
        }
        __syncthreads();   // sync B: chunk n landed and visible

        // pack codes for chunk n from staged adj/et
        if (tid < 256) {
            uint4 a4 = adjS[buf * 256 + tid];
            uint4 t4 = etS[buf * 256 + tid];
            unsigned int c0 = a4.x ? t4.x : 50u;
            unsigned int c1 = a4.y ? t4.y : 50u;
            unsigned int c2 = a4.z ? t4.z : 50u;
            unsigned int c3 = a4.w ? t4.w : 50u;
            codesS[buf * 384 + crr * 12 + cww] = c0 | (c1 << 8) | (c2 << 16) | (c3 << 24);
        }
        __syncthreads();   // sync C: codes visible

        const unsigned int* whb = WhS + buf * WBUF;
        const unsigned int* cR0 = codesS + buf * 384 + r0 * 12;
        const unsigned int* cR1 = codesS + buf * 384 + r1 * 12;
        const int jc = n * CJ_;
#pragma unroll
        for (int k8 = 0; k8 < 4; k8++) {
            const int jl  = k8 * 8;
            const int jgl = jc + jl;
            uint2 cw0 = *(const uint2*)&cR0[k8 * 2];
            uint2 cw1 = *(const uint2*)&cR1[k8 * 2];

            float s2c0 = s2s[(jgl + t) * 8 + h];
            float s2c1 = s2s[(jgl + t + 4) * 8 + h];

            float e00 = s1a + s2c0 + embH[__byte_perm(cw0.x, 0, selA)];
            float e10 = s1b + s2c0 + embH[__byte_perm(cw1.x, 0, selA)];
            float e01 = s1a + s2c1 + embH[__byte_perm(cw0.y, 0, selA)];
            float e11 = s1b + s2c1 + embH[__byte_perm(cw1.y, 0, selA)];
            e00 = fmaxf(e00, 0.2f * e00);
            e10 = fmaxf(e10, 0.2f * e10);
            e01 = fmaxf(e01, 0.2f * e01);
            e11 = fmaxf(e11, 0.2f * e11);
            // convert first; den from converted weights (num/den consistent)
            float a0  = tf32f(ex2f(e00));
            float a1f = tf32f(ex2f(e10));
            float a2f = tf32f(ex2f(e01));
            float a3f = tf32f(ex2f(e11));
            den0 += a0 + a2f;
            den1 += a1f + a3f;

            uint4 B0v = *(const uint4*)&whb[(jl + t) * WSTR + h * 32 + g * 4];
            uint4 B1v = *(const uint4*)&whb[(jl + t + 4) * WSTR + h * 32 + g * 4];
            mma_tf32(acc[0], a0, a1f, a2f, a3f, __uint_as_float(B0v.x), __uint_as_float(B1v.x));
            mma_tf32(acc[1], a0, a1f, a2f, a3f, __uint_as_float(B0v.y), __uint_as_float(B1v.y));
            mma_tf32(acc[2], a0, a1f, a2f, a3f, __uint_as_float(B0v.z), __uint_as_float(B1v.z));
            mma_tf32(acc[3], a0, a1f, a2f, a3f, __uint_as_float(B0v.w), __uint_as_float(B1v.w));
        }
    }

    den0 += __shfl_xor_sync(0xffffffffu, den0, 1);
    den0 += __shfl_xor_sync(0xffffffffu, den0, 2);
    den1 += __shfl_xor_sync(0xffffffffu, den1, 1);
    den1 += __shfl_xor_sync(0xffffffffu, den1, 2);

    __syncthreads();  // all MMA reads of WhS done; alias as outS
    if (t == 0) {
        denS[r0 * 8 + h] = den0;
        denS[r1 * 8 + h] = den1;
    }
#pragma unroll
    for (int nf = 0; nf < 4; nf++) {
        int col = h * 32 + nf * 8 + t * 2;
        *(float2*)&outS[r0 * WSTR + col] = make_float2(acc[nf][0], acc[nf][1]);
        *(float2*)&outS[r1 * WSTR + col] = make_float2(acc[nf][2], acc[nf][3]);
    }
    __syncthreads();

#pragma unroll
    for (int rr = warp * 2; rr < warp * 2 + 2; rr++) {
        float inv = 1.0f / denS[rr * 8 + (lane >> 2)];
        float4 v0 = *(float4*)&outS[rr * WSTR + lane * 8];
        float4 v1 = *(float4*)&outS[rr * WSTR + lane * 8 + 4];
        float v[8] = {v0.x, v0.y, v0.z, v0.w, v1.x, v1.y, v1.z, v1.w};
        float s = 0.f, q = 0.f;
#pragma unroll
        for (int k = 0; k < 8; k++) {
            v[k] *= inv;
            s += v[k];
            q = fmaf(v[k], v[k], q);
        }
#pragma unroll
        for (int off = 16; off; off >>= 1) {
            s += __shfl_xor_sync(0xffffffffu, s, off);
            q += __shfl_xor_sync(0xffffffffu, q, off);
        }
        float mu   = s * (1.0f / 256.0f);
        float var  = q * (1.0f / 256.0f) - mu * mu;
        float rstd = rsqrtf(var + 1e-5f);
        float o[8];
#pragma unroll
        for (int k = 0; k < 8; k++) {
            int d = lane * 8 + k;
            float y = (v[k] - mu) * rstd * gs[d] + bs[d];
            o[k] = (y > 0.f) ? y : (__expf(y) - 1.0f);
        }
        float4* op = (float4*)(out + ((size_t)b * N_ + iBase + rr) * 256);
        op[lane * 2]     = make_float4(o[0], o[1], o[2], o[3]);
        op[lane * 2 + 1] = make_float4(o[4], o[5], o[6], o[7]);
    }
}

// ---------------------------------------------------------------------------
extern "C" void kernel_launch(void* const* d_in, const int* in_sizes, int n_in,
                              void* d_out, int out_size) {
    (void)in_sizes; (void)n_in; (void)out_size;
    const float* x     = (const float*)d_in[0];
    const int*   adj   = (const int*)d_in[1];
    const int*   et    = (const int*)d_in[2];
    const float* W     = (const float*)d_in[3];
    const float* a1    = (const float*)d_in[4];
    const float* a2    = (const float*)d_in[5];
    const float* eemb  = (const float*)d_in[6];
    const float* gamma = (const float*)d_in[7];
    const float* beta  = (const float*)d_in[8];
    float* out = (float*)d_out;

    // K1: Wh = x @ W (2xTF32 split tensor cores) + fused s1/s2 scores
    {
        dim3 grid(OUTF_ / 128, (B_ * N_) / 64);
        gemm_score_kernel<<<grid, 256>>>(x, W, a1, a2);
    }
    // K2: fused attention (tensor cores) + LN + ELU
    {
        const int smemBytes = SMEM_FLOATS * 4;  // 109568
        cudaFuncSetAttribute(attn_kernel, cudaFuncAttributeMaxDynamicSharedMemorySize,
                             smemBytes);
        dim3 grid(N_ / IT_, B_);
        attn_kernel<<<grid, 512, smemBytes>>>(adj, et, eemb, gamma, beta, out);
    }
}

// round 14
// speedup vs baseline: 1.0751x; 1.0751x over previous
#include <cuda_runtime.h>
#include <cstdint>

#define B_    16
#define N_    512
#define INF_  256
#define OUTF_ 256
#define H_    8
#define NET_  50
#define LOG2E 1.4426950408889634f
#define IT_   32      // i-rows per block (attn)
#define CJ_   32      // j-chunk (attn)
#define WSTR  264     // WhS row stride (u32)
#define WBUF  (CJ_ * WSTR)   // 8448

// SMEM offsets (float units)
#define OFF_S2    0
#define OFF_EMB   4096
#define OFF_G     4608
#define OFF_B     4864
#define OFF_S1    5120
#define OFF_DEN   5376
#define OFF_CODES 5632              // 2 x 384 u32 (32 rows x 12-padded, 16B-aligned)
#define OFF_ADJ   6400              // 2 x 256 uint4 = 2048 u32
#define OFF_ET    8448              // 2048 u32
#define OFF_WH    10496             // 2 x 8448 u32
#define SMEM_FLOATS (OFF_WH + 2 * WBUF)   // 27392 -> 109568 B

// Scratch (allocation-free rule: __device__ globals)
// g_Wh: row-major [row][256]; within each head's 32 dims permuted:
// storage pos p = g*4 + nf  <->  dim dl = nf*8 + g.
__device__ float g_Wh[B_ * N_ * OUTF_];
__device__ float g_s1[B_ * N_ * H_];      // pre-scaled by log2e
__device__ float g_s2[B_ * N_ * H_];

// ---------------------------------------------------------------------------
__device__ __forceinline__ float ex2f(float x) {   // MUFU.EX2
    float r;
    asm("ex2.approx.f32 %0, %1;" : "=f"(r) : "f"(x));
    return r;
}
__device__ __forceinline__ float tf32f(float f) {
    unsigned int u;
    asm("cvt.rna.tf32.f32 %0, %1;" : "=r"(u) : "f"(f));
    return __uint_as_float(u);
}
__device__ __forceinline__ void mma_tf32(float acc[4], float a0, float a1f,
                                         float a2f, float a3f, float b0, float b1) {
    asm volatile(
        "mma.sync.aligned.m16n8k8.row.col.f32.tf32.tf32.f32 "
        "{%0,%1,%2,%3}, {%4,%5,%6,%7}, {%8,%9}, {%0,%1,%2,%3};"
        : "+f"(acc[0]), "+f"(acc[1]), "+f"(acc[2]), "+f"(acc[3])
        : "r"(__float_as_uint(a0)), "r"(__float_as_uint(a1f)),
          "r"(__float_as_uint(a2f)), "r"(__float_as_uint(a3f)),
          "r"(__float_as_uint(b0)), "r"(__float_as_uint(b1)));
}
__device__ __forceinline__ void cp_async16(unsigned int smem_addr, const void* gptr) {
    asm volatile("cp.async.cg.shared.global [%0], [%1], 16;" ::"r"(smem_addr), "l"(gptr));
}
__device__ __forceinline__ unsigned int smem_u32(const void* p) {
    unsigned int a;
    asm("{ .reg .u64 t; cvta.to.shared.u64 t, %1; cvt.u32.u64 %0, t; }" : "=r"(a) : "l"(p));
    return a;
}

// ---------------------------------------------------------------------------
// K1: Wh = x @ W via 2xTF32-split tensor-core GEMM + fused s1/s2 epilogue.
// M-tile 64, N-tile 128, k-chunk 16. Permuted g_Wh stores now vectorized:
// fragment values acc[0..3][c] are 4 consecutive permuted addresses -> STG.128.
// ---------------------------------------------------------------------------
#define ASTR 20
#define BSTR 136
__global__ __launch_bounds__(256, 2) void gemm_score_kernel(
    const float* __restrict__ A, const float* __restrict__ Bw,
    const float* __restrict__ a1, const float* __restrict__ a2) {
    __shared__ float Ahi[64 * ASTR], Alo[64 * ASTR];
    __shared__ float Bs[16 * BSTR];
    __shared__ float a1s[32], a2s[32];

    const int tid = threadIdx.x;
    const int m0 = blockIdx.y * 64;
    const int n0 = blockIdx.x * 128;
    if (tid < 32) { a1s[tid] = a1[tid]; a2s[tid] = a2[tid]; }

    const int warp = tid >> 5, lane = tid & 31;
    const int wm = warp >> 1, wn = warp & 1;
    const int g = lane >> 2, t = lane & 3;

    float acc[8][4];
#pragma unroll
    for (int nf = 0; nf < 8; nf++)
#pragma unroll
        for (int c = 0; c < 4; c++) acc[nf][c] = 0.f;

    float4 va, vb[2];
    va = ((const float4*)A)[(size_t)(m0 + (tid >> 2)) * 64 + (tid & 3)];
#pragma unroll
    for (int it = 0; it < 2; it++) {
        int idx = tid + it * 256;
        vb[it] = ((const float4*)Bw)[(size_t)(idx >> 5) * 64 + (n0 >> 2) + (idx & 31)];
    }

    for (int k0 = 0; k0 < INF_; k0 += 16) {
        __syncthreads();   // previous chunk's smem readers done
        {
            float4 v = va;
            float4 hi, lo;
            hi.x = tf32f(v.x); lo.x = tf32f(v.x - hi.x);
            hi.y = tf32f(v.y); lo.y = tf32f(v.y - hi.y);
            hi.z = tf32f(v.z); lo.z = tf32f(v.z - hi.z);
            hi.w = tf32f(v.w); lo.w = tf32f(v.w - hi.w);
            int off = (tid >> 2) * ASTR + (tid & 3) * 4;
            *(float4*)&Ahi[off] = hi;
            *(float4*)&Alo[off] = lo;
        }
#pragma unroll
        for (int it = 0; it < 2; it++) {
            int idx = tid + it * 256;
            float4 v = vb[it];
            float4 hi;
            hi.x = tf32f(v.x);
            hi.y = tf32f(v.y);
            hi.z = tf32f(v.z);
            hi.w = tf32f(v.w);
            *(float4*)&Bs[(idx >> 5) * BSTR + (idx & 31) * 4] = hi;
        }
        __syncthreads();
        // issue next chunk's LDGs; they complete under the MMA section
        if (k0 + 16 < INF_) {
            va = ((const float4*)A)[(size_t)(m0 + (tid >> 2)) * 64 +
                                    ((k0 + 16) >> 2) + (tid & 3)];
#pragma unroll
            for (int it = 0; it < 2; it++) {
                int idx = tid + it * 256;
                vb[it] = ((const float4*)Bw)[(size_t)(k0 + 16 + (idx >> 5)) * 64 +
                                             (n0 >> 2) + (idx & 31)];
            }
        }
#pragma unroll
        for (int k8 = 0; k8 < 2; k8++) {
            const int kk = k8 * 8 + t;
            float ah[4], al[4];
            {
                int r = (wm * 16 + g) * ASTR;
                ah[0] = Ahi[r + kk];
                ah[1] = Ahi[r + 8 * ASTR + kk];
                ah[2] = Ahi[r + kk + 4];
                ah[3] = Ahi[r + 8 * ASTR + kk + 4];
                al[0] = Alo[r + kk];
                al[1] = Alo[r + 8 * ASTR + kk];
                al[2] = Alo[r + kk + 4];
                al[3] = Alo[r + 8 * ASTR + kk + 4];
            }
#pragma unroll
            for (int nf = 0; nf < 8; nf++) {
                int c = wn * 64 + nf * 8 + g;
                float bh0 = Bs[kk * BSTR + c];
                float bh1 = Bs[(kk + 4) * BSTR + c];
                mma_tf32(acc[nf], ah[0], ah[1], ah[2], ah[3], bh0, bh1);
                mma_tf32(acc[nf], al[0], al[1], al[2], al[3], bh0, bh1);
            }
        }
    }

    // ---- epilogue: scores (fp32) + permuted tf32 Wh store (vectorized) ----
    const int hb = (n0 >> 5) + wn * 2;
    {
        float pA1[2] = {0.f, 0.f}, pA2[2] = {0.f, 0.f};
        float pB1[2] = {0.f, 0.f}, pB2[2] = {0.f, 0.f};
#pragma unroll
        for (int nf = 0; nf < 8; nf++) {
            int d0 = (nf * 8 + t * 2) & 31;
            int hh = nf >> 2;
            float c0 = acc[nf][0], c1 = acc[nf][1];
            float c2 = acc[nf][2], c3 = acc[nf][3];
            pA1[hh] += c0 * a1s[d0] + c1 * a1s[d0 + 1];
            pA2[hh] += c0 * a2s[d0] + c1 * a2s[d0 + 1];
            pB1[hh] += c2 * a1s[d0] + c3 * a1s[d0 + 1];
            pB2[hh] += c2 * a2s[d0] + c3 * a2s[d0 + 1];
        }
#pragma unroll
        for (int hh = 0; hh < 2; hh++) {
            pA1[hh] += __shfl_xor_sync(0xffffffffu, pA1[hh], 1);
            pA1[hh] += __shfl_xor_sync(0xffffffffu, pA1[hh], 2);
            pA2[hh] += __shfl_xor_sync(0xffffffffu, pA2[hh], 1);
            pA2[hh] += __shfl_xor_sync(0xffffffffu, pA2[hh], 2);
            pB1[hh] += __shfl_xor_sync(0xffffffffu, pB1[hh], 1);
            pB1[hh] += __shfl_xor_sync(0xffffffffu, pB1[hh], 2);
            pB2[hh] += __shfl_xor_sync(0xffffffffu, pB2[hh], 1);
            pB2[hh] += __shfl_xor_sync(0xffffffffu, pB2[hh], 2);
        }
        int rA = m0 + wm * 16 + g;
        int rB = rA + 8;
        if (t == 0) {
            g_s1[(size_t)rA * 8 + hb]     = pA1[0] * LOG2E;
            g_s1[(size_t)rA * 8 + hb + 1] = pA1[1] * LOG2E;
            g_s2[(size_t)rA * 8 + hb]     = pA2[0] * LOG2E;
            g_s2[(size_t)rA * 8 + hb + 1] = pA2[1] * LOG2E;
            g_s1[(size_t)rB * 8 + hb]     = pB1[0] * LOG2E;
            g_s1[(size_t)rB * 8 + hb + 1] = pB1[1] * LOG2E;
            g_s2[(size_t)rB * 8 + hb]     = pB2[0] * LOG2E;
            g_s2[(size_t)rB * 8 + hb + 1] = pB2[1] * LOG2E;
        }
        // Vectorized permuted store: for each head half hh, fragment values
        // acc[4*hh + (0..3)][c] land at 4 consecutive columns -> STG.128.
#pragma unroll
        for (int hh = 0; hh < 2; hh++) {
            int h_idx = wn * 2 + hh;
            int col0 = n0 + h_idx * 32 + 8 * t;     // 16B-aligned
            float4 v0 = make_float4(tf32f(acc[4 * hh + 0][0]), tf32f(acc[4 * hh + 1][0]),
                                    tf32f(acc[4 * hh + 2][0]), tf32f(acc[4 * hh + 3][0]));
            float4 v1 = make_float4(tf32f(acc[4 * hh + 0][1]), tf32f(acc[4 * hh + 1][1]),
                                    tf32f(acc[4 * hh + 2][1]), tf32f(acc[4 * hh + 3][1]));
            float4 v2 = make_float4(tf32f(acc[4 * hh + 0][2]), tf32f(acc[4 * hh + 1][2]),
                                    tf32f(acc[4 * hh + 2][2]), tf32f(acc[4 * hh + 3][2]));
            float4 v3 = make_float4(tf32f(acc[4 * hh + 0][3]), tf32f(acc[4 * hh + 1][3]),
                                    tf32f(acc[4 * hh + 2][3]), tf32f(acc[4 * hh + 3][3]));
            *(float4*)&g_Wh[(size_t)rA * 256 + col0]     = v0;
            *(float4*)&g_Wh[(size_t)rA * 256 + col0 + 4] = v1;
            *(float4*)&g_Wh[(size_t)rB * 256 + col0]     = v2;
            *(float4*)&g_Wh[(size_t)rB * 256 + col0 + 4] = v3;
        }
    }
}

// ---------------------------------------------------------------------------
// K2: fused attention, cp.async double-buffered pipeline. (unchanged)
// ---------------------------------------------------------------------------
__global__ void __launch_bounds__(512, 2)
attn_kernel(const int* __restrict__ adj, const int* __restrict__ et,
            const float* __restrict__ edge_emb,
            const float* __restrict__ gamma, const float* __restrict__ beta,
            float* __restrict__ out) {
    extern __shared__ float sm[];
    float* s2s  = sm + OFF_S2;
    float* embT = sm + OFF_EMB;
    float* gs   = sm + OFF_G;
    float* bs   = sm + OFF_B;
    float* s1s  = sm + OFF_S1;
    float* denS = sm + OFF_DEN;
    unsigned int* codesS = (unsigned int*)(sm + OFF_CODES);   // 2 x (32 x 12)
    uint4*        adjS   = (uint4*)(sm + OFF_ADJ);            // 2 x 256
    uint4*        etS    = (uint4*)(sm + OFF_ET);             // 2 x 256
    unsigned int* WhS    = (unsigned int*)(sm + OFF_WH);      // 2 x WBUF
    float*        outS   = (float*)(sm + OFF_WH);

    const int b     = blockIdx.y;
    const int iBase = blockIdx.x * IT_;
    const int tid   = threadIdx.x;
    const int warp  = tid >> 5, lane = tid & 31;

    const unsigned int adjU = smem_u32(adjS);
    const unsigned int etU  = smem_u32(etS);
    const unsigned int whU  = smem_u32(WhS);

    // one-time staging
    const float* s2g = g_s2 + (size_t)b * N_ * H_;
    for (int i = tid; i < N_ * H_; i += 512) s2s[i] = s2g[i];
    {
        int h = tid >> 6, e = tid & 63;
        embT[tid] = (e < NET_) ? edge_emb[e * H_ + h] * LOG2E : -12000.0f;
    }
    if (tid < 256) { gs[tid] = gamma[tid]; bs[tid] = beta[tid]; }
    if (tid < IT_ * H_) s1s[tid] = g_s1[((size_t)b * N_ + iBase) * H_ + tid];

    const int it = warp >> 3;
    const int h  = warp & 7;
    const int g  = lane >> 2;
    const int t  = lane & 3;
    const int r0 = it * 16 + g;
    const int r1 = r0 + 8;
    const unsigned int selA = 0x4440u | (unsigned int)t;
    const float* embH = embT + h * 64;

    const int4* adjRow = (const int4*)(adj + ((size_t)(b * N_ + iBase)) * N_);
    const int4* etRow  = (const int4*)(et  + ((size_t)(b * N_ + iBase)) * N_);
    const uint4* whg   = (const uint4*)(g_Wh + (size_t)b * N_ * 256);
    const int crr = tid >> 3, cww = tid & 7;   // code staging role (tid<256)

    // prologue: chunk 0 -> buffer 0
#pragma unroll
    for (int k2 = 0; k2 < 4; k2++) {
        int idx = tid + k2 * 512;
        int rr = idx >> 6, cc = idx & 63;
        cp_async16(whU + (unsigned)(rr * WSTR + cc * 4) * 4u, whg + idx);
    }
    if (tid < 256) {
        cp_async16(adjU + (unsigned)tid * 16u, adjRow + crr * (N_ / 4) + cww);
        cp_async16(etU + (unsigned)tid * 16u, etRow + crr * (N_ / 4) + cww);
    }
    asm volatile("cp.async.commit_group;");

    __syncthreads();
    const float s1a = s1s[r0 * 8 + h];
    const float s1b = s1s[r1 * 8 + h];

    float acc[4][4];
#pragma unroll
    for (int nf = 0; nf < 4; nf++)
#pragma unroll
        for (int k = 0; k < 4; k++) acc[nf][k] = 0.f;
    float den0 = 0.f, den1 = 0.f;

    for (int n = 0; n < 16; n++) {
        const int buf = n & 1;
        __syncthreads();   // sync A: compute of chunk n-1 (buffer 1-buf) drained
        if (n < 15) {
            const uint4* src = whg + (n + 1) * (CJ_ * 64);
            unsigned int dstb = whU + (unsigned)(1 - buf) * (WBUF * 4u);
#pragma unroll
            for (int k2 = 0; k2 < 4; k2++) {
                int idx = tid + k2 * 512;
                int rr = idx >> 6, cc = idx & 63;
                cp_async16(dstb + (unsigned)(rr * WSTR + cc * 4) * 4u, src + idx);
            }
            if (tid < 256) {
                unsigned int bo = (unsigned)(1 - buf) * 4096u + (unsigned)tid * 16u;
                cp_async16(adjU + bo, adjRow + crr * (N_ / 4) + (n + 1) * 8 + cww);
                cp_async16(etU + bo, etRow + crr * (N_ / 4) + (n + 1) * 8 + cww);
            }
            asm volatile("cp.async.commit_group;");
            asm volatile("cp.async.wait_group 1;");
        } else {
            asm volatile("cp.async.wait_group 0;");
        }
        __syncthreads();   // sync B: chunk n landed and visible

        // pack codes for chunk n from staged adj/et
        if (tid < 256) {
            uint4 a4 = adjS[buf * 256 + tid];
            uint4 t4 = etS[buf * 256 + tid];
            unsigned int c0 = a4.x ? t4.x : 50u;
            unsigned int c1 = a4.y ? t4.y : 50u;
            unsigned int c2 = a4.z ? t4.z : 50u;
            unsigned int c3 = a4.w ? t4.w : 50u;
            codesS[buf * 384 + crr * 12 + cww] = c0 | (c1 << 8) | (c2 << 16) | (c3 << 24);
        }
        __syncthreads();   // sync C: codes visible

        const unsigned int* whb = WhS + buf * WBUF;
        const unsigned int* cR0 = codesS + buf * 384 + r0 * 12;
        const unsigned int* cR1 = codesS + buf * 384 + r1 * 12;
        const int jc = n * CJ_;
#pragma unroll
        for (int k8 = 0; k8 < 4; k8++) {
            const int jl  = k8 * 8;
            const int jgl = jc + jl;
            uint2 cw0 = *(const uint2*)&cR0[k8 * 2];
            uint2 cw1 = *(const uint2*)&cR1[k8 * 2];

            float s2c0 = s2s[(jgl + t) * 8 + h];
            float s2c1 = s2s[(jgl + t + 4) * 8 + h];

            float e00 = s1a + s2c0 + embH[__byte_perm(cw0.x, 0, selA)];
            float e10 = s1b + s2c0 + embH[__byte_perm(cw1.x, 0, selA)];
            float e01 = s1a + s2c1 + embH[__byte_perm(cw0.y, 0, selA)];
            float e11 = s1b + s2c1 + embH[__byte_perm(cw1.y, 0, selA)];
            e00 = fmaxf(e00, 0.2f * e00);
            e10 = fmaxf(e10, 0.2f * e10);
            e01 = fmaxf(e01, 0.2f * e01);
            e11 = fmaxf(e11, 0.2f * e11);
            // convert first; den from converted weights (num/den consistent)
            float a0  = tf32f(ex2f(e00));
            float a1f = tf32f(ex2f(e10));
            float a2f = tf32f(ex2f(e01));
            float a3f = tf32f(ex2f(e11));
            den0 += a0 + a2f;
            den1 += a1f + a3f;

            uint4 B0v = *(const uint4*)&whb[(jl + t) * WSTR + h * 32 + g * 4];
            uint4 B1v = *(const uint4*)&whb[(jl + t + 4) * WSTR + h * 32 + g * 4];
            mma_tf32(acc[0], a0, a1f, a2f, a3f, __uint_as_float(B0v.x), __uint_as_float(B1v.x));
            mma_tf32(acc[1], a0, a1f, a2f, a3f, __uint_as_float(B0v.y), __uint_as_float(B1v.y));
            mma_tf32(acc[2], a0, a1f, a2f, a3f, __uint_as_float(B0v.z), __uint_as_float(B1v.z));
            mma_tf32(acc[3], a0, a1f, a2f, a3f, __uint_as_float(B0v.w), __uint_as_float(B1v.w));
        }
    }

    den0 += __shfl_xor_sync(0xffffffffu, den0, 1);
    den0 += __shfl_xor_sync(0xffffffffu, den0, 2);
    den1 += __shfl_xor_sync(0xffffffffu, den1, 1);
    den1 += __shfl_xor_sync(0xffffffffu, den1, 2);

    __syncthreads();  // all MMA reads of WhS done; alias as outS
    if (t == 0) {
        denS[r0 * 8 + h] = den0;
        denS[r1 * 8 + h] = den1;
    }
#pragma unroll
    for (int nf = 0; nf < 4; nf++) {
        int col = h * 32 + nf * 8 + t * 2;
        *(float2*)&outS[r0 * WSTR + col] = make_float2(acc[nf][0], acc[nf][1]);
        *(float2*)&outS[r1 * WSTR + col] = make_float2(acc[nf][2], acc[nf][3]);
    }
    __syncthreads();

#pragma unroll
    for (int rr = warp * 2; rr < warp * 2 + 2; rr++) {
        float inv = 1.0f / denS[rr * 8 + (lane >> 2)];
        float4 v0 = *(float4*)&outS[rr * WSTR + lane * 8];
        float4 v1 = *(float4*)&outS[rr * WSTR + lane * 8 + 4];
        float v[8] = {v0.x, v0.y, v0.z, v0.w, v1.x, v1.y, v1.z, v1.w};
        float s = 0.f, q = 0.f;
#pragma unroll
        for (int k = 0; k < 8; k++) {
            v[k] *= inv;
            s += v[k];
            q = fmaf(v[k], v[k], q);
        }
#pragma unroll
        for (int off = 16; off; off >>= 1) {
            s += __shfl_xor_sync(0xffffffffu, s, off);
            q += __shfl_xor_sync(0xffffffffu, q, off);
        }
        float mu   = s * (1.0f / 256.0f);
        float var  = q * (1.0f / 256.0f) - mu * mu;
        float rstd = rsqrtf(var + 1e-5f);
        float o[8];
#pragma unroll
        for (int k = 0; k < 8; k++) {
            int d = lane * 8 + k;
            float y = (v[k] - mu) * rstd * gs[d] + bs[d];
            o[k] = (y > 0.f) ? y : (__expf(y) - 1.0f);
        }
        float4* op = (float4*)(out + ((size_t)b * N_ + iBase + rr) * 256);
        op[lane * 2]     = make_float4(o[0], o[1], o[2], o[3]);
        op[lane * 2 + 1] = make_float4(o[4], o[5], o[6], o[7]);
    }
}

// ---------------------------------------------------------------------------
extern "C" void kernel_launch(void* const* d_in, const int* in_sizes, int n_in,
                              void* d_out, int out_size) {
    (void)in_sizes; (void)n_in; (void)out_size;
    const float* x     = (const float*)d_in[0];
    const int*   adj   = (const int*)d_in[1];
    const int*   et    = (const int*)d_in[2];
    const float* W     = (const float*)d_in[3];
    const float* a1    = (const float*)d_in[4];
    const float* a2    = (const float*)d_in[5];
    const float* eemb  = (const float*)d_in[6];
    const float* gamma = (const float*)d_in[7];
    const float* beta  = (const float*)d_in[8];
    float* out = (float*)d_out;

    // K1: Wh = x @ W (2xTF32 split tensor cores) + fused s1/s2 scores
    {
        dim3 grid(OUTF_ / 128, (B_ * N_) / 64);
        gemm_score_kernel<<<grid, 256>>>(x, W, a1, a2);
    }
    // K2: fused attention (tensor cores) + LN + ELU
    {
        const int smemBytes = SMEM_FLOATS * 4;  // 109568
        cudaFuncSetAttribute(attn_kernel, cudaFuncAttributeMaxDynamicSharedMemorySize,
                             smemBytes);
        dim3 grid(N_ / IT_, B_);
        attn_kernel<<<grid, 512, smemBytes>>>(adj, et, eemb, gamma, beta, out);
    }
}

// round 16
// speedup vs baseline: 1.1212x; 1.0429x over previous
#include <cuda_runtime.h>
#include <cstdint>

#define B_    16
#define N_    512
#define INF_  256
#define OUTF_ 256
#define H_    8
#define NET_  50
#define LOG2E 1.4426950408889634f
#define IT_   32      // i-rows per block (attn)
#define CJ_   32      // j-chunk (attn)
#define WSTR  264     // WhS row stride (u32)
#define WBUF  (CJ_ * WSTR)   // 8448

// SMEM offsets (float units)
#define OFF_S2    0
#define OFF_EMB   4096
#define OFF_G     4608
#define OFF_B     4864
#define OFF_S1    5120
#define OFF_DEN   5376
#define OFF_CODES 5632              // 2 x 384 u32 (32 rows x 12-padded, 16B-aligned)
#define OFF_ADJ   6400              // 2 x 256 uint4 = 2048 u32
#define OFF_ET    8448              // 2048 u32
#define OFF_WH    10496             // 2 x 8448 u32
#define SMEM_FLOATS (OFF_WH + 2 * WBUF)   // 27392 -> 109568 B

// Scratch (allocation-free rule: __device__ globals)
// g_Wh: row-major [row][256]; within each head's 32 dims permuted:
// storage pos p = g*4 + nf  <->  dim dl = nf*8 + g.
__device__ float g_Wh[B_ * N_ * OUTF_];
__device__ float g_s1[B_ * N_ * H_];      // pre-scaled by log2e
__device__ float g_s2[B_ * N_ * H_];

// ---------------------------------------------------------------------------
__device__ __forceinline__ float ex2f(float x) {   // MUFU.EX2
    float r;
    asm("ex2.approx.f32 %0, %1;" : "=f"(r) : "f"(x));
    return r;
}
__device__ __forceinline__ float tf32f(float f) {
    unsigned int u;
    asm("cvt.rna.tf32.f32 %0, %1;" : "=r"(u) : "f"(f));
    return __uint_as_float(u);
}
__device__ __forceinline__ void mma_tf32(float acc[4], float a0, float a1f,
                                         float a2f, float a3f, float b0, float b1) {
    asm volatile(
        "mma.sync.aligned.m16n8k8.row.col.f32.tf32.tf32.f32 "
        "{%0,%1,%2,%3}, {%4,%5,%6,%7}, {%8,%9}, {%0,%1,%2,%3};"
        : "+f"(acc[0]), "+f"(acc[1]), "+f"(acc[2]), "+f"(acc[3])
        : "r"(__float_as_uint(a0)), "r"(__float_as_uint(a1f)),
          "r"(__float_as_uint(a2f)), "r"(__float_as_uint(a3f)),
          "r"(__float_as_uint(b0)), "r"(__float_as_uint(b1)));
}
__device__ __forceinline__ void cp_async16(unsigned int smem_addr, const void* gptr) {
    asm volatile("cp.async.cg.shared.global [%0], [%1], 16;" ::"r"(smem_addr), "l"(gptr));
}
__device__ __forceinline__ unsigned int smem_u32(const void* p) {
    unsigned int a;
    asm("{ .reg .u64 t; cvta.to.shared.u64 t, %1; cvt.u32.u64 %0, t; }" : "=r"(a) : "l"(p));
    return a;
}

// ---------------------------------------------------------------------------
// K1: Wh = x @ W via 2xTF32-split tensor-core GEMM + fused s1/s2 epilogue.
// (unchanged from round 14)
// ---------------------------------------------------------------------------
#define ASTR 20
#define BSTR 136
__global__ __launch_bounds__(256, 2) void gemm_score_kernel(
    const float* __restrict__ A, const float* __restrict__ Bw,
    const float* __restrict__ a1, const float* __restrict__ a2) {
    __shared__ float Ahi[64 * ASTR], Alo[64 * ASTR];
    __shared__ float Bs[16 * BSTR];
    __shared__ float a1s[32], a2s[32];

    const int tid = threadIdx.x;
    const int m0 = blockIdx.y * 64;
    const int n0 = blockIdx.x * 128;
    if (tid < 32) { a1s[tid] = a1[tid]; a2s[tid] = a2[tid]; }

    const int warp = tid >> 5, lane = tid & 31;
    const int wm = warp >> 1, wn = warp & 1;
    const int g = lane >> 2, t = lane & 3;

    float acc[8][4];
#pragma unroll
    for (int nf = 0; nf < 8; nf++)
#pragma unroll
        for (int c = 0; c < 4; c++) acc[nf][c] = 0.f;

    float4 va, vb[2];
    va = ((const float4*)A)[(size_t)(m0 + (tid >> 2)) * 64 + (tid & 3)];
#pragma unroll
    for (int it = 0; it < 2; it++) {
        int idx = tid + it * 256;
        vb[it] = ((const float4*)Bw)[(size_t)(idx >> 5) * 64 + (n0 >> 2) + (idx & 31)];
    }

    for (int k0 = 0; k0 < INF_; k0 += 16) {
        __syncthreads();   // previous chunk's smem readers done
        {
            float4 v = va;
            float4 hi, lo;
            hi.x = tf32f(v.x); lo.x = tf32f(v.x - hi.x);
            hi.y = tf32f(v.y); lo.y = tf32f(v.y - hi.y);
            hi.z = tf32f(v.z); lo.z = tf32f(v.z - hi.z);
            hi.w = tf32f(v.w); lo.w = tf32f(v.w - hi.w);
            int off = (tid >> 2) * ASTR + (tid & 3) * 4;
            *(float4*)&Ahi[off] = hi;
            *(float4*)&Alo[off] = lo;
        }
#pragma unroll
        for (int it = 0; it < 2; it++) {
            int idx = tid + it * 256;
            float4 v = vb[it];
            float4 hi;
            hi.x = tf32f(v.x);
            hi.y = tf32f(v.y);
            hi.z = tf32f(v.z);
            hi.w = tf32f(v.w);
            *(float4*)&Bs[(idx >> 5) * BSTR + (idx & 31) * 4] = hi;
        }
        __syncthreads();
        // issue next chunk's LDGs; they complete under the MMA section
        if (k0 + 16 < INF_) {
            va = ((const float4*)A)[(size_t)(m0 + (tid >> 2)) * 64 +
                                    ((k0 + 16) >> 2) + (tid & 3)];
#pragma unroll
            for (int it = 0; it < 2; it++) {
                int idx = tid + it * 256;
                vb[it] = ((const float4*)Bw)[(size_t)(k0 + 16 + (idx >> 5)) * 64 +
                                             (n0 >> 2) + (idx & 31)];
            }
        }
#pragma unroll
        for (int k8 = 0; k8 < 2; k8++) {
            const int kk = k8 * 8 + t;
            float ah[4], al[4];
            {
                int r = (wm * 16 + g) * ASTR;
                ah[0] = Ahi[r + kk];
                ah[1] = Ahi[r + 8 * ASTR + kk];
                ah[2] = Ahi[r + kk + 4];
                ah[3] = Ahi[r + 8 * ASTR + kk + 4];
                al[0] = Alo[r + kk];
                al[1] = Alo[r + 8 * ASTR + kk];
                al[2] = Alo[r + kk + 4];
                al[3] = Alo[r + 8 * ASTR + kk + 4];
            }
#pragma unroll
            for (int nf = 0; nf < 8; nf++) {
                int c = wn * 64 + nf * 8 + g;
                float bh0 = Bs[kk * BSTR + c];
                float bh1 = Bs[(kk + 4) * BSTR + c];
                mma_tf32(acc[nf], ah[0], ah[1], ah[2], ah[3], bh0, bh1);
                mma_tf32(acc[nf], al[0], al[1], al[2], al[3], bh0, bh1);
            }
        }
    }

    // ---- epilogue: scores (fp32) + permuted tf32 Wh store (vectorized) ----
    const int hb = (n0 >> 5) + wn * 2;
    {
        float pA1[2] = {0.f, 0.f}, pA2[2] = {0.f, 0.f};
        float pB1[2] = {0.f, 0.f}, pB2[2] = {0.f, 0.f};
#pragma unroll
        for (int nf = 0; nf < 8; nf++) {
            int d0 = (nf * 8 + t * 2) & 31;
            int hh = nf >> 2;
            float c0 = acc[nf][0], c1 = acc[nf][1];
            float c2 = acc[nf][2], c3 = acc[nf][3];
            pA1[hh] += c0 * a1s[d0] + c1 * a1s[d0 + 1];
            pA2[hh] += c0 * a2s[d0] + c1 * a2s[d0 + 1];
            pB1[hh] += c2 * a1s[d0] + c3 * a1s[d0 + 1];
            pB2[hh] += c2 * a2s[d0] + c3 * a2s[d0 + 1];
        }
#pragma unroll
        for (int hh = 0; hh < 2; hh++) {
            pA1[hh] += __shfl_xor_sync(0xffffffffu, pA1[hh], 1);
            pA1[hh] += __shfl_xor_sync(0xffffffffu, pA1[hh], 2);
            pA2[hh] += __shfl_xor_sync(0xffffffffu, pA2[hh], 1);
            pA2[hh] += __shfl_xor_sync(0xffffffffu, pA2[hh], 2);
            pB1[hh] += __shfl_xor_sync(0xffffffffu, pB1[hh], 1);
            pB1[hh] += __shfl_xor_sync(0xffffffffu, pB1[hh], 2);
            pB2[hh] += __shfl_xor_sync(0xffffffffu, pB2[hh], 1);
            pB2[hh] += __shfl_xor_sync(0xffffffffu, pB2[hh], 2);
        }
        int rA = m0 + wm * 16 + g;
        int rB = rA + 8;
        if (t == 0) {
            g_s1[(size_t)rA * 8 + hb]     = pA1[0] * LOG2E;
            g_s1[(size_t)rA * 8 + hb + 1] = pA1[1] * LOG2E;
            g_s2[(size_t)rA * 8 + hb]     = pA2[0] * LOG2E;
            g_s2[(size_t)rA * 8 + hb + 1] = pA2[1] * LOG2E;
            g_s1[(size_t)rB * 8 + hb]     = pB1[0] * LOG2E;
            g_s1[(size_t)rB * 8 + hb + 1] = pB1[1] * LOG2E;
            g_s2[(size_t)rB * 8 + hb]     = pB2[0] * LOG2E;
            g_s2[(size_t)rB * 8 + hb + 1] = pB2[1] * LOG2E;
        }
#pragma unroll
        for (int hh = 0; hh < 2; hh++) {
            int h_idx = wn * 2 + hh;
            int col0 = n0 + h_idx * 32 + 8 * t;     // 16B-aligned
            float4 v0 = make_float4(tf32f(acc[4 * hh + 0][0]), tf32f(acc[4 * hh + 1][0]),
                                    tf32f(acc[4 * hh + 2][0]), tf32f(acc[4 * hh + 3][0]));
            float4 v1 = make_float4(tf32f(acc[4 * hh + 0][1]), tf32f(acc[4 * hh + 1][1]),
                                    tf32f(acc[4 * hh + 2][1]), tf32f(acc[4 * hh + 3][1]));
            float4 v2 = make_float4(tf32f(acc[4 * hh + 0][2]), tf32f(acc[4 * hh + 1][2]),
                                    tf32f(acc[4 * hh + 2][2]), tf32f(acc[4 * hh + 3][2]));
            float4 v3 = make_float4(tf32f(acc[4 * hh + 0][3]), tf32f(acc[4 * hh + 1][3]),
                                    tf32f(acc[4 * hh + 2][3]), tf32f(acc[4 * hh + 3][3]));
            *(float4*)&g_Wh[(size_t)rA * 256 + col0]     = v0;
            *(float4*)&g_Wh[(size_t)rA * 256 + col0 + 4] = v1;
            *(float4*)&g_Wh[(size_t)rB * 256 + col0]     = v2;
            *(float4*)&g_Wh[(size_t)rB * 256 + col0 + 4] = v3;
        }
    }
}

// ---------------------------------------------------------------------------
// K2: fused attention, cp.async pipeline.
// Prefetch distances: WhS = 1 chunk, adj/et = 2 chunks. Codes for chunk n+1
// are packed at iteration n (after sync B), so the k8 loop needs NO third
// barrier — next iteration's sync A/B order pack-writes before code-reads.
// A-operands feed mma.tf32 raw (HW truncation); no per-weight cvt.
// ---------------------------------------------------------------------------
__global__ void __launch_bounds__(512, 2)
attn_kernel(const int* __restrict__ adj, const int* __restrict__ et,
            const float* __restrict__ edge_emb,
            const float* __restrict__ gamma, const float* __restrict__ beta,
            float* __restrict__ out) {
    extern __shared__ float sm[];
    float* s2s  = sm + OFF_S2;
    float* embT = sm + OFF_EMB;
    float* gs   = sm + OFF_G;
    float* bs   = sm + OFF_B;
    float* s1s  = sm + OFF_S1;
    float* denS = sm + OFF_DEN;
    unsigned int* codesS = (unsigned int*)(sm + OFF_CODES);   // 2 x (32 x 12)
    uint4*        adjS   = (uint4*)(sm + OFF_ADJ);            // 2 x 256
    uint4*        etS    = (uint4*)(sm + OFF_ET);             // 2 x 256
    unsigned int* WhS    = (unsigned int*)(sm + OFF_WH);      // 2 x WBUF
    float*        outS   = (float*)(sm + OFF_WH);

    const int b     = blockIdx.y;
    const int iBase = blockIdx.x * IT_;
    const int tid   = threadIdx.x;
    const int warp  = tid >> 5, lane = tid & 31;

    const unsigned int adjU = smem_u32(adjS);
    const unsigned int etU  = smem_u32(etS);
    const unsigned int whU  = smem_u32(WhS);

    // one-time staging
    const float* s2g = g_s2 + (size_t)b * N_ * H_;
    for (int i = tid; i < N_ * H_; i += 512) s2s[i] = s2g[i];
    {
        int h = tid >> 6, e = tid & 63;
        embT[tid] = (e < NET_) ? edge_emb[e * H_ + h] * LOG2E : -12000.0f;
    }
    if (tid < 256) { gs[tid] = gamma[tid]; bs[tid] = beta[tid]; }
    if (tid < IT_ * H_) s1s[tid] = g_s1[((size_t)b * N_ + iBase) * H_ + tid];

    const int it = warp >> 3;
    const int h  = warp & 7;
    const int g  = lane >> 2;
    const int t  = lane & 3;
    const int r0 = it * 16 + g;
    const int r1 = r0 + 8;
    const unsigned int selA = 0x4440u | (unsigned int)t;
    const float* embH = embT + h * 64;

    const int4* adjRow = (const int4*)(adj + ((size_t)(b * N_ + iBase)) * N_);
    const int4* etRow  = (const int4*)(et  + ((size_t)(b * N_ + iBase)) * N_);
    const uint4* whg   = (const uint4*)(g_Wh + (size_t)b * N_ * 256);
    const int crr = tid >> 3, cww = tid & 7;   // code staging role (tid<256)

    // prologue: WhS chunk0 -> buf0; adj/et chunks 0 and 1 -> abuf 0 and 1
#pragma unroll
    for (int k2 = 0; k2 < 4; k2++) {
        int idx = tid + k2 * 512;
        int rr = idx >> 6, cc = idx & 63;
        cp_async16(whU + (unsigned)(rr * WSTR + cc * 4) * 4u, whg + idx);
    }
    if (tid < 256) {
        cp_async16(adjU + (unsigned)tid * 16u, adjRow + crr * (N_ / 4) + cww);
        cp_async16(etU + (unsigned)tid * 16u, etRow + crr * (N_ / 4) + cww);
        cp_async16(adjU + 4096u + (unsigned)tid * 16u, adjRow + crr * (N_ / 4) + 8 + cww);
        cp_async16(etU + 4096u + (unsigned)tid * 16u, etRow + crr * (N_ / 4) + 8 + cww);
    }
    asm volatile("cp.async.commit_group;");
    asm volatile("cp.async.wait_group 0;");
    __syncthreads();   // staging + prologue cp.async visible

    // pack codes for chunk 0 (sync A of iteration 0 orders this before compute)
    if (tid < 256) {
        uint4 a4 = adjS[tid];
        uint4 t4 = etS[tid];
        unsigned int c0 = a4.x ? t4.x : 50u;
        unsigned int c1 = a4.y ? t4.y : 50u;
        unsigned int c2 = a4.z ? t4.z : 50u;
        unsigned int c3 = a4.w ? t4.w : 50u;
        codesS[crr * 12 + cww] = c0 | (c1 << 8) | (c2 << 16) | (c3 << 24);
    }

    const float s1a = s1s[r0 * 8 + h];
    const float s1b = s1s[r1 * 8 + h];

    float acc[4][4];
#pragma unroll
    for (int nf = 0; nf < 4; nf++)
#pragma unroll
        for (int k = 0; k < 4; k++) acc[nf][k] = 0.f;
    float den0 = 0.f, den1 = 0.f;

#pragma unroll 2
    for (int n = 0; n < 16; n++) {
        const int buf = n & 1;
        __syncthreads();   // sync A: compute n-1 + pack-reads drained
        if (n < 15) {
            // WhS chunk n+1 -> buffer 1-buf
            const uint4* src = whg + (n + 1) * (CJ_ * 64);
            unsigned int dstb = whU + (unsigned)(1 - buf) * (WBUF * 4u);
#pragma unroll
            for (int k2 = 0; k2 < 4; k2++) {
                int idx = tid + k2 * 512;
                int rr = idx >> 6, cc = idx & 63;
                cp_async16(dstb + (unsigned)(rr * WSTR + cc * 4) * 4u, src + idx);
            }
            // adj/et chunk n+2 -> abuf (n+2)&1 == buf
            if (tid < 256 && n < 14) {
                unsigned int bo = (unsigned)buf * 4096u + (unsigned)tid * 16u;
                cp_async16(adjU + bo, adjRow + crr * (N_ / 4) + (n + 2) * 8 + cww);
                cp_async16(etU + bo, etRow + crr * (N_ / 4) + (n + 2) * 8 + cww);
            }
            asm volatile("cp.async.commit_group;");
            asm volatile("cp.async.wait_group 1;");
        } else {
            asm volatile("cp.async.wait_group 0;");
        }
        __syncthreads();   // sync B: WhS n + adj/et n+1 landed and visible

        // pack codes for chunk n+1 (buffer 1-buf); no further barrier needed
        if (n < 15 && tid < 256) {
            int pb = 1 - buf;
            uint4 a4 = adjS[pb * 256 + tid];
            uint4 t4 = etS[pb * 256 + tid];
            unsigned int c0 = a4.x ? t4.x : 50u;
            unsigned int c1 = a4.y ? t4.y : 50u;
            unsigned int c2 = a4.z ? t4.z : 50u;
            unsigned int c3 = a4.w ? t4.w : 50u;
            codesS[pb * 384 + crr * 12 + cww] = c0 | (c1 << 8) | (c2 << 16) | (c3 << 24);
        }

        const unsigned int* whb = WhS + buf * WBUF;
        const unsigned int* cR0 = codesS + buf * 384 + r0 * 12;
        const unsigned int* cR1 = codesS + buf * 384 + r1 * 12;
        const int jc = n * CJ_;
#pragma unroll
        for (int k8 = 0; k8 < 4; k8++) {
            const int jl  = k8 * 8;
            const int jgl = jc + jl;
            uint2 cw0 = *(const uint2*)&cR0[k8 * 2];
            uint2 cw1 = *(const uint2*)&cR1[k8 * 2];

            float s2c0 = s2s[(jgl + t) * 8 + h];
            float s2c1 = s2s[(jgl + t + 4) * 8 + h];

            float e00 = s1a + s2c0 + embH[__byte_perm(cw0.x, 0, selA)];
            float e10 = s1b + s2c0 + embH[__byte_perm(cw1.x, 0, selA)];
            float e01 = s1a + s2c1 + embH[__byte_perm(cw0.y, 0, selA)];
            float e11 = s1b + s2c1 + embH[__byte_perm(cw1.y, 0, selA)];
            e00 = fmaxf(e00, 0.2f * e00);
            e10 = fmaxf(e10, 0.2f * e10);
            e01 = fmaxf(e01, 0.2f * e01);
            e11 = fmaxf(e11, 0.2f * e11);
            // raw weights: MMA truncates to tf32 internally; den from the
            // same raw values (truncation deficit mostly cancels in ratio)
            float a0  = ex2f(e00);
            float a1f = ex2f(e10);
            float a2f = ex2f(e01);
            float a3f = ex2f(e11);
            den0 += a0 + a2f;
            den1 += a1f + a3f;

            uint4 B0v = *(const uint4*)&whb[(jl + t) * WSTR + h * 32 + g * 4];
            uint4 B1v = *(const uint4*)&whb[(jl + t + 4) * WSTR + h * 32 + g * 4];
            mma_tf32(acc[0], a0, a1f, a2f, a3f, __uint_as_float(B0v.x), __uint_as_float(B1v.x));
            mma_tf32(acc[1], a0, a1f, a2f, a3f, __uint_as_float(B0v.y), __uint_as_float(B1v.y));
            mma_tf32(acc[2], a0, a1f, a2f, a3f, __uint_as_float(B0v.z), __uint_as_float(B1v.z));
            mma_tf32(acc[3], a0, a1f, a2f, a3f, __uint_as_float(B0v.w), __uint_as_float(B1v.w));
        }
    }

    den0 += __shfl_xor_sync(0xffffffffu, den0, 1);
    den0 += __shfl_xor_sync(0xffffffffu, den0, 2);
    den1 += __shfl_xor_sync(0xffffffffu, den1, 1);
    den1 += __shfl_xor_sync(0xffffffffu, den1, 2);

    __syncthreads();  // all MMA reads of WhS done; alias as outS
    if (t == 0) {
        denS[r0 * 8 + h] = den0;
        denS[r1 * 8 + h] = den1;
    }
#pragma unroll
    for (int nf = 0; nf < 4; nf++) {
        int col = h * 32 + nf * 8 + t * 2;
        *(float2*)&outS[r0 * WSTR + col] = make_float2(acc[nf][0], acc[nf][1]);
        *(float2*)&outS[r1 * WSTR + col] = make_float2(acc[nf][2], acc[nf][3]);
    }
    __syncthreads();

#pragma unroll
    for (int rr = warp * 2; rr < warp * 2 + 2; rr++) {
        float inv = 1.0f / denS[rr * 8 + (lane >> 2)];
        float4 v0 = *(float4*)&outS[rr * WSTR + lane * 8];
        float4 v1 = *(float4*)&outS[rr * WSTR + lane * 8 + 4];
        float v[8] = {v0.x, v0.y, v0.z, v0.w, v1.x, v1.y, v1.z, v1.w};
        float s = 0.f, q = 0.f;
#pragma unroll
        for (int k = 0; k < 8; k++) {
            v[k] *= inv;
            s += v[k];
            q = fmaf(v[k], v[k], q);
        }
#pragma unroll
        for (int off = 16; off; off >>= 1) {
            s += __shfl_xor_sync(0xffffffffu, s, off);
            q += __shfl_xor_sync(0xffffffffu, q, off);
        }
        float mu   = s * (1.0f / 256.0f);
        float var  = q * (1.0f / 256.0f) - mu * mu;
        float rstd = rsqrtf(var + 1e-5f);
        float o[8];
#pragma unroll
        for (int k = 0; k < 8; k++) {
            int d = lane * 8 + k;
            float y = (v[k] - mu) * rstd * gs[d] + bs[d];
            o[k] = (y > 0.f) ? y : (__expf(y) - 1.0f);
        }
        float4* op = (float4*)(out + ((size_t)b * N_ + iBase + rr) * 256);
        op[lane * 2]     = make_float4(o[0], o[1], o[2], o[3]);
        op[lane * 2 + 1] = make_float4(o[4], o[5], o[6], o[7]);
    }
}

// ---------------------------------------------------------------------------
extern "C" void kernel_launch(void* const* d_in, const int* in_sizes, int n_in,
                              void* d_out, int out_size) {
    (void)in_sizes; (void)n_in; (void)out_size;
    const float* x     = (const float*)d_in[0];
    const int*   adj   = (const int*)d_in[1];
    const int*   et    = (const int*)d_in[2];
    const float* W     = (const float*)d_in[3];
    const float* a1    = (const float*)d_in[4];
    const float* a2    = (const float*)d_in[5];
    const float* eemb  = (const float*)d_in[6];
    const float* gamma = (const float*)d_in[7];
    const float* beta  = (const float*)d_in[8];
    float* out = (float*)d_out;

    // K1: Wh = x @ W (2xTF32 split tensor cores) + fused s1/s2 scores
    {
        dim3 grid(OUTF_ / 128, (B_ * N_) / 64);
        gemm_score_kernel<<<grid, 256>>>(x, W, a1, a2);
    }
    // K2: fused attention (tensor cores) + LN + ELU
    {
        const int smemBytes = SMEM_FLOATS * 4;  // 109568
        cudaFuncSetAttribute(attn_kernel, cudaFuncAttributeMaxDynamicSharedMemorySize,
                             smemBytes);
        dim3 grid(N_ / IT_, B_);
        attn_kernel<<<grid, 512, smemBytes>>>(adj, et, eemb, gamma, beta, out);
    }
}

// round 17
// speedup vs baseline: 1.1439x; 1.0202x over previous
#include <cuda_runtime.h>
#include <cstdint>

#define B_    16
#define N_    512
#define INF_  256
#define OUTF_ 256
#define H_    8
#define NET_  50
#define LOG2E 1.4426950408889634f
#define IT_   32      // i-rows per block (attn)
#define CJ_   32      // j-chunk (attn)
#define WSTR  264     // WhS row stride (u32)
#define WBUF  (CJ_ * WSTR)   // 8448

// SMEM offsets (float units)
#define OFF_S2    0
#define OFF_EMB   4096
#define OFF_G     4608
#define OFF_B     4864
#define OFF_S1    5120
#define OFF_DEN   5376
#define OFF_CODES 5632              // 2 x 384 u32 (32 rows x 12-padded, 16B-aligned)
#define OFF_ADJ   6400              // 2 x 256 uint4 = 2048 u32
#define OFF_ET    8448              // 2048 u32
#define OFF_WH    10496             // 2 x 8448 u32
#define SMEM_FLOATS (OFF_WH + 2 * WBUF)   // 27392 -> 109568 B

// Scratch (allocation-free rule: __device__ globals)
// g_Wh: row-major [row][256]; within each head's 32 dims permuted:
// storage pos p = g*4 + nf  <->  dim dl = nf*8 + g.
__device__ float g_Wh[B_ * N_ * OUTF_];
__device__ float g_s1[B_ * N_ * H_];      // pre-scaled by log2e
__device__ float g_s2[B_ * N_ * H_];

// ---------------------------------------------------------------------------
__device__ __forceinline__ float ex2f(float x) {   // MUFU.EX2
    float r;
    asm("ex2.approx.f32 %0, %1;" : "=f"(r) : "f"(x));
    return r;
}
__device__ __forceinline__ float tf32f(float f) {
    unsigned int u;
    asm("cvt.rna.tf32.f32 %0, %1;" : "=r"(u) : "f"(f));
    return __uint_as_float(u);
}
__device__ __forceinline__ void mma_tf32(float acc[4], float a0, float a1f,
                                         float a2f, float a3f, float b0, float b1) {
    asm volatile(
        "mma.sync.aligned.m16n8k8.row.col.f32.tf32.tf32.f32 "
        "{%0,%1,%2,%3}, {%4,%5,%6,%7}, {%8,%9}, {%0,%1,%2,%3};"
        : "+f"(acc[0]), "+f"(acc[1]), "+f"(acc[2]), "+f"(acc[3])
        : "r"(__float_as_uint(a0)), "r"(__float_as_uint(a1f)),
          "r"(__float_as_uint(a2f)), "r"(__float_as_uint(a3f)),
          "r"(__float_as_uint(b0)), "r"(__float_as_uint(b1)));
}
__device__ __forceinline__ void cp_async16(unsigned int smem_addr, const void* gptr) {
    asm volatile("cp.async.cg.shared.global [%0], [%1], 16;" ::"r"(smem_addr), "l"(gptr));
}
__device__ __forceinline__ unsigned int smem_u32(const void* p) {
    unsigned int a;
    asm("{ .reg .u64 t; cvta.to.shared.u64 t, %1; cvt.u32.u64 %0, t; }" : "=r"(a) : "l"(p));
    return a;
}

// ---------------------------------------------------------------------------
// K1: Wh = x @ W via 2xTF32-split tensor-core GEMM + fused s1/s2 epilogue.
// Double-buffered SMEM staging, ONE barrier per k-chunk: the barrier at iter n
// separates iter n-1's MMA reads of buffer p (before it, program order) from
// iter n+1's writes to buffer p (after it). Convert overlaps other warps' MMA.
// ---------------------------------------------------------------------------
#define ASTR 20
#define BSTR 136
__global__ __launch_bounds__(256, 2) void gemm_score_kernel(
    const float* __restrict__ A, const float* __restrict__ Bw,
    const float* __restrict__ a1, const float* __restrict__ a2) {
    __shared__ float Ahi[2][64 * ASTR], Alo[2][64 * ASTR];
    __shared__ float Bs[2][16 * BSTR];
    __shared__ float a1s[32], a2s[32];

    const int tid = threadIdx.x;
    const int m0 = blockIdx.y * 64;
    const int n0 = blockIdx.x * 128;
    if (tid < 32) { a1s[tid] = a1[tid]; a2s[tid] = a2[tid]; }

    const int warp = tid >> 5, lane = tid & 31;
    const int wm = warp >> 1, wn = warp & 1;
    const int g = lane >> 2, t = lane & 3;

    float acc[8][4];
#pragma unroll
    for (int nf = 0; nf < 8; nf++)
#pragma unroll
        for (int c = 0; c < 4; c++) acc[nf][c] = 0.f;

    float4 va, vb[2];
    va = ((const float4*)A)[(size_t)(m0 + (tid >> 2)) * 64 + (tid & 3)];
#pragma unroll
    for (int it = 0; it < 2; it++) {
        int idx = tid + it * 256;
        vb[it] = ((const float4*)Bw)[(size_t)(idx >> 5) * 64 + (n0 >> 2) + (idx & 31)];
    }

#pragma unroll 1
    for (int kc = 0; kc < 16; kc++) {
        const int p = kc & 1;
        // convert current regs into buffer p
        {
            float4 v = va;
            float4 hi, lo;
            hi.x = tf32f(v.x); lo.x = tf32f(v.x - hi.x);
            hi.y = tf32f(v.y); lo.y = tf32f(v.y - hi.y);
            hi.z = tf32f(v.z); lo.z = tf32f(v.z - hi.z);
            hi.w = tf32f(v.w); lo.w = tf32f(v.w - hi.w);
            int off = (tid >> 2) * ASTR + (tid & 3) * 4;
            *(float4*)&Ahi[p][off] = hi;
            *(float4*)&Alo[p][off] = lo;
        }
#pragma unroll
        for (int it = 0; it < 2; it++) {
            int idx = tid + it * 256;
            float4 v = vb[it];
            float4 hi;
            hi.x = tf32f(v.x);
            hi.y = tf32f(v.y);
            hi.z = tf32f(v.z);
            hi.w = tf32f(v.w);
            *(float4*)&Bs[p][(idx >> 5) * BSTR + (idx & 31) * 4] = hi;
        }
        // prefetch next chunk's LDGs (regs free after cvt; WAR safe)
        if (kc + 1 < 16) {
            int k0n = (kc + 1) * 16;
            va = ((const float4*)A)[(size_t)(m0 + (tid >> 2)) * 64 +
                                    (k0n >> 2) + (tid & 3)];
#pragma unroll
            for (int it = 0; it < 2; it++) {
                int idx = tid + it * 256;
                vb[it] = ((const float4*)Bw)[(size_t)(k0n + (idx >> 5)) * 64 +
                                             (n0 >> 2) + (idx & 31)];
            }
        }
        __syncthreads();   // single barrier: buffer p writes visible; see header
#pragma unroll
        for (int k8 = 0; k8 < 2; k8++) {
            const int kk = k8 * 8 + t;
            float ah[4], al[4];
            {
                int r = (wm * 16 + g) * ASTR;
                ah[0] = Ahi[p][r + kk];
                ah[1] = Ahi[p][r + 8 * ASTR + kk];
                ah[2] = Ahi[p][r + kk + 4];
                ah[3] = Ahi[p][r + 8 * ASTR + kk + 4];
                al[0] = Alo[p][r + kk];
                al[1] = Alo[p][r + 8 * ASTR + kk];
                al[2] = Alo[p][r + kk + 4];
                al[3] = Alo[p][r + 8 * ASTR + kk + 4];
            }
#pragma unroll
            for (int nf = 0; nf < 8; nf++) {
                int c = wn * 64 + nf * 8 + g;
                float bh0 = Bs[p][kk * BSTR + c];
                float bh1 = Bs[p][(kk + 4) * BSTR + c];
                mma_tf32(acc[nf], ah[0], ah[1], ah[2], ah[3], bh0, bh1);
                mma_tf32(acc[nf], al[0], al[1], al[2], al[3], bh0, bh1);
            }
        }
    }

    // ---- epilogue: scores (fp32) + permuted tf32 Wh store (vectorized) ----
    const int hb = (n0 >> 5) + wn * 2;
    {
        float pA1[2] = {0.f, 0.f}, pA2[2] = {0.f, 0.f};
        float pB1[2] = {0.f, 0.f}, pB2[2] = {0.f, 0.f};
#pragma unroll
        for (int nf = 0; nf < 8; nf++) {
            int d0 = (nf * 8 + t * 2) & 31;
            int hh = nf >> 2;
            float c0 = acc[nf][0], c1 = acc[nf][1];
            float c2 = acc[nf][2], c3 = acc[nf][3];
            pA1[hh] += c0 * a1s[d0] + c1 * a1s[d0 + 1];
            pA2[hh] += c0 * a2s[d0] + c1 * a2s[d0 + 1];
            pB1[hh] += c2 * a1s[d0] + c3 * a1s[d0 + 1];
            pB2[hh] += c2 * a2s[d0] + c3 * a2s[d0 + 1];
        }
#pragma unroll
        for (int hh = 0; hh < 2; hh++) {
            pA1[hh] += __shfl_xor_sync(0xffffffffu, pA1[hh], 1);
            pA1[hh] += __shfl_xor_sync(0xffffffffu, pA1[hh], 2);
            pA2[hh] += __shfl_xor_sync(0xffffffffu, pA2[hh], 1);
            pA2[hh] += __shfl_xor_sync(0xffffffffu, pA2[hh], 2);
            pB1[hh] += __shfl_xor_sync(0xffffffffu, pB1[hh], 1);
            pB1[hh] += __shfl_xor_sync(0xffffffffu, pB1[hh], 2);
            pB2[hh] += __shfl_xor_sync(0xffffffffu, pB2[hh], 1);
            pB2[hh] += __shfl_xor_sync(0xffffffffu, pB2[hh], 2);
        }
        int rA = m0 + wm * 16 + g;
        int rB = rA + 8;
        if (t == 0) {
            g_s1[(size_t)rA * 8 + hb]     = pA1[0] * LOG2E;
            g_s1[(size_t)rA * 8 + hb + 1] = pA1[1] * LOG2E;
            g_s2[(size_t)rA * 8 + hb]     = pA2[0] * LOG2E;
            g_s2[(size_t)rA * 8 + hb + 1] = pA2[1] * LOG2E;
            g_s1[(size_t)rB * 8 + hb]     = pB1[0] * LOG2E;
            g_s1[(size_t)rB * 8 + hb + 1] = pB1[1] * LOG2E;
            g_s2[(size_t)rB * 8 + hb]     = pB2[0] * LOG2E;
            g_s2[(size_t)rB * 8 + hb + 1] = pB2[1] * LOG2E;
        }
#pragma unroll
        for (int hh = 0; hh < 2; hh++) {
            int h_idx = wn * 2 + hh;
            int col0 = n0 + h_idx * 32 + 8 * t;     // 16B-aligned
            float4 v0 = make_float4(tf32f(acc[4 * hh + 0][0]), tf32f(acc[4 * hh + 1][0]),
                                    tf32f(acc[4 * hh + 2][0]), tf32f(acc[4 * hh + 3][0]));
            float4 v1 = make_float4(tf32f(acc[4 * hh + 0][1]), tf32f(acc[4 * hh + 1][1]),
                                    tf32f(acc[4 * hh + 2][1]), tf32f(acc[4 * hh + 3][1]));
            float4 v2 = make_float4(tf32f(acc[4 * hh + 0][2]), tf32f(acc[4 * hh + 1][2]),
                                    tf32f(acc[4 * hh + 2][2]), tf32f(acc[4 * hh + 3][2]));
            float4 v3 = make_float4(tf32f(acc[4 * hh + 0][3]), tf32f(acc[4 * hh + 1][3]),
                                    tf32f(acc[4 * hh + 2][3]), tf32f(acc[4 * hh + 3][3]));
            *(float4*)&g_Wh[(size_t)rA * 256 + col0]     = v0;
            *(float4*)&g_Wh[(size_t)rA * 256 + col0 + 4] = v1;
            *(float4*)&g_Wh[(size_t)rB * 256 + col0]     = v2;
            *(float4*)&g_Wh[(size_t)rB * 256 + col0 + 4] = v3;
        }
    }
}

// ---------------------------------------------------------------------------
// K2: fused attention, cp.async pipeline. (byte-identical to round 16)
// ---------------------------------------------------------------------------
__global__ void __launch_bounds__(512, 2)
attn_kernel(const int* __restrict__ adj, const int* __restrict__ et,
            const float* __restrict__ edge_emb,
            const float* __restrict__ gamma, const float* __restrict__ beta,
            float* __restrict__ out) {
    extern __shared__ float sm[];
    float* s2s  = sm + OFF_S2;
    float* embT = sm + OFF_EMB;
    float* gs   = sm + OFF_G;
    float* bs   = sm + OFF_B;
    float* s1s  = sm + OFF_S1;
    float* denS = sm + OFF_DEN;
    unsigned int* codesS = (unsigned int*)(sm + OFF_CODES);   // 2 x (32 x 12)
    uint4*        adjS   = (uint4*)(sm + OFF_ADJ);            // 2 x 256
    uint4*        etS    = (uint4*)(sm + OFF_ET);             // 2 x 256
    unsigned int* WhS    = (unsigned int*)(sm + OFF_WH);      // 2 x WBUF
    float*        outS   = (float*)(sm + OFF_WH);

    const int b     = blockIdx.y;
    const int iBase = blockIdx.x * IT_;
    const int tid   = threadIdx.x;
    const int warp  = tid >> 5, lane = tid & 31;

    const unsigned int adjU = smem_u32(adjS);
    const unsigned int etU  = smem_u32(etS);
    const unsigned int whU  = smem_u32(WhS);

    // one-time staging
    const float* s2g = g_s2 + (size_t)b * N_ * H_;
    for (int i = tid; i < N_ * H_; i += 512) s2s[i] = s2g[i];
    {
        int h = tid >> 6, e = tid & 63;
        embT[tid] = (e < NET_) ? edge_emb[e * H_ + h] * LOG2E : -12000.0f;
    }
    if (tid < 256) { gs[tid] = gamma[tid]; bs[tid] = beta[tid]; }
    if (tid < IT_ * H_) s1s[tid] = g_s1[((size_t)b * N_ + iBase) * H_ + tid];

    const int it = warp >> 3;
    const int h  = warp & 7;
    const int g  = lane >> 2;
    const int t  = lane & 3;
    const int r0 = it * 16 + g;
    const int r1 = r0 + 8;
    const unsigned int selA = 0x4440u | (unsigned int)t;
    const float* embH = embT + h * 64;

    const int4* adjRow = (const int4*)(adj + ((size_t)(b * N_ + iBase)) * N_);
    const int4* etRow  = (const int4*)(et  + ((size_t)(b * N_ + iBase)) * N_);
    const uint4* whg   = (const uint4*)(g_Wh + (size_t)b * N_ * 256);
    const int crr = tid >> 3, cww = tid & 7;   // code staging role (tid<256)

    // prologue: WhS chunk0 -> buf0; adj/et chunks 0 and 1 -> abuf 0 and 1
#pragma unroll
    for (int k2 = 0; k2 < 4; k2++) {
        int idx = tid + k2 * 512;
        int rr = idx >> 6, cc = idx & 63;
        cp_async16(whU + (unsigned)(rr * WSTR + cc * 4) * 4u, whg + idx);
    }
    if (tid < 256) {
        cp_async16(adjU + (unsigned)tid * 16u, adjRow + crr * (N_ / 4) + cww);
        cp_async16(etU + (unsigned)tid * 16u, etRow + crr * (N_ / 4) + cww);
        cp_async16(adjU + 4096u + (unsigned)tid * 16u, adjRow + crr * (N_ / 4) + 8 + cww);
        cp_async16(etU + 4096u + (unsigned)tid * 16u, etRow + crr * (N_ / 4) + 8 + cww);
    }
    asm volatile("cp.async.commit_group;");
    asm volatile("cp.async.wait_group 0;");
    __syncthreads();   // staging + prologue cp.async visible

    // pack codes for chunk 0 (sync A of iteration 0 orders this before compute)
    if (tid < 256) {
        uint4 a4 = adjS[tid];
        uint4 t4 = etS[tid];
        unsigned int c0 = a4.x ? t4.x : 50u;
        unsigned int c1 = a4.y ? t4.y : 50u;
        unsigned int c2 = a4.z ? t4.z : 50u;
        unsigned int c3 = a4.w ? t4.w : 50u;
        codesS[crr * 12 + cww] = c0 | (c1 << 8) | (c2 << 16) | (c3 << 24);
    }

    const float s1a = s1s[r0 * 8 + h];
    const float s1b = s1s[r1 * 8 + h];

    float acc[4][4];
#pragma unroll
    for (int nf = 0; nf < 4; nf++)
#pragma unroll
        for (int k = 0; k < 4; k++) acc[nf][k] = 0.f;
    float den0 = 0.f, den1 = 0.f;

#pragma unroll 2
    for (int n = 0; n < 16; n++) {
        const int buf = n & 1;
        __syncthreads();   // sync A: compute n-1 + pack-reads drained
        if (n < 15) {
            // WhS chunk n+1 -> buffer 1-buf
            const uint4* src = whg + (n + 1) * (CJ_ * 64);
            unsigned int dstb = whU + (unsigned)(1 - buf) * (WBUF * 4u);
#pragma unroll
            for (int k2 = 0; k2 < 4; k2++) {
                int idx = tid + k2 * 512;
                int rr = idx >> 6, cc = idx & 63;
                cp_async16(dstb + (unsigned)(rr * WSTR + cc * 4) * 4u, src + idx);
            }
            // adj/et chunk n+2 -> abuf (n+2)&1 == buf
            if (tid < 256 && n < 14) {
                unsigned int bo = (unsigned)buf * 4096u + (unsigned)tid * 16u;
                cp_async16(adjU + bo, adjRow + crr * (N_ / 4) + (n + 2) * 8 + cww);
                cp_async16(etU + bo, etRow + crr * (N_ / 4) + (n + 2) * 8 + cww);
            }
            asm volatile("cp.async.commit_group;");
            asm volatile("cp.async.wait_group 1;");
        } else {
            asm volatile("cp.async.wait_group 0;");
        }
        __syncthreads();   // sync B: WhS n + adj/et n+1 landed and visible

        // pack codes for chunk n+1 (buffer 1-buf); no further barrier needed
        if (n < 15 && tid < 256) {
            int pb = 1 - buf;
            uint4 a4 = adjS[pb * 256 + tid];
            uint4 t4 = etS[pb * 256 + tid];
            unsigned int c0 = a4.x ? t4.x : 50u;
            unsigned int c1 = a4.y ? t4.y : 50u;
            unsigned int c2 = a4.z ? t4.z : 50u;
            unsigned int c3 = a4.w ? t4.w : 50u;
            codesS[pb * 384 + crr * 12 + cww] = c0 | (c1 << 8) | (c2 << 16) | (c3 << 24);
        }

        const unsigned int* whb = WhS + buf * WBUF;
        const unsigned int* cR0 = codesS + buf * 384 + r0 * 12;
        const unsigned int* cR1 = codesS + buf * 384 + r1 * 12;
        const int jc = n * CJ_;
#pragma unroll
        for (int k8 = 0; k8 < 4; k8++) {
            const int jl  = k8 * 8;
            const int jgl = jc + jl;
            uint2 cw0 = *(const uint2*)&cR0[k8 * 2];
            uint2 cw1 = *(const uint2*)&cR1[k8 * 2];

            float s2c0 = s2s[(jgl + t) * 8 + h];
            float s2c1 = s2s[(jgl + t + 4) * 8 + h];

            float e00 = s1a + s2c0 + embH[__byte_perm(cw0.x, 0, selA)];
            float e10 = s1b + s2c0 + embH[__byte_perm(cw1.x, 0, selA)];
            float e01 = s1a + s2c1 + embH[__byte_perm(cw0.y, 0, selA)];
            float e11 = s1b + s2c1 + embH[__byte_perm(cw1.y, 0, selA)];
            e00 = fmaxf(e00, 0.2f * e00);
            e10 = fmaxf(e10, 0.2f * e10);
            e01 = fmaxf(e01, 0.2f * e01);
            e11 = fmaxf(e11, 0.2f * e11);
            // raw weights: MMA truncates to tf32 internally; den from the
            // same raw values (truncation deficit mostly cancels in ratio)
            float a0  = ex2f(e00);
            float a1f = ex2f(e10);
            float a2f = ex2f(e01);
            float a3f = ex2f(e11);
            den0 += a0 + a2f;
            den1 += a1f + a3f;

            uint4 B0v = *(const uint4*)&whb[(jl + t) * WSTR + h * 32 + g * 4];
            uint4 B1v = *(const uint4*)&whb[(jl + t + 4) * WSTR + h * 32 + g * 4];
            mma_tf32(acc[0], a0, a1f, a2f, a3f, __uint_as_float(B0v.x), __uint_as_float(B1v.x));
            mma_tf32(acc[1], a0, a1f, a2f, a3f, __uint_as_float(B0v.y), __uint_as_float(B1v.y));
            mma_tf32(acc[2], a0, a1f, a2f, a3f, __uint_as_float(B0v.z), __uint_as_float(B1v.z));
            mma_tf32(acc[3], a0, a1f, a2f, a3f, __uint_as_float(B0v.w), __uint_as_float(B1v.w));
        }
    }

    den0 += __shfl_xor_sync(0xffffffffu, den0, 1);
    den0 += __shfl_xor_sync(0xffffffffu, den0, 2);
    den1 += __shfl_xor_sync(0xffffffffu, den1, 1);
    den1 += __shfl_xor_sync(0xffffffffu, den1, 2);

    __syncthreads();  // all MMA reads of WhS done; alias as outS
    if (t == 0) {
        denS[r0 * 8 + h] = den0;
        denS[r1 * 8 + h] = den1;
    }
#pragma unroll
    for (int nf = 0; nf < 4; nf++) {
        int col = h * 32 + nf * 8 + t * 2;
        *(float2*)&outS[r0 * WSTR + col] = make_float2(acc[nf][0], acc[nf][1]);
        *(float2*)&outS[r1 * WSTR + col] = make_float2(acc[nf][2], acc[nf][3]);
    }
    __syncthreads();

#pragma unroll
    for (int rr = warp * 2; rr < warp * 2 + 2; rr++) {
        float inv = 1.0f / denS[rr * 8 + (lane >> 2)];
        float4 v0 = *(float4*)&outS[rr * WSTR + lane * 8];
        float4 v1 = *(float4*)&outS[rr * WSTR + lane * 8 + 4];
        float v[8] = {v0.x, v0.y, v0.z, v0.w, v1.x, v1.y, v1.z, v1.w};
        float s = 0.f, q = 0.f;
#pragma unroll
        for (int k = 0; k < 8; k++) {
            v[k] *= inv;
            s += v[k];
            q = fmaf(v[k], v[k], q);
        }
#pragma unroll
        for (int off = 16; off; off >>= 1) {
            s += __shfl_xor_sync(0xffffffffu, s, off);
            q += __shfl_xor_sync(0xffffffffu, q, off);
        }
        float mu   = s * (1.0f / 256.0f);
        float var  = q * (1.0f / 256.0f) - mu * mu;
        float rstd = rsqrtf(var + 1e-5f);
        float o[8];
#pragma unroll
        for (int k = 0; k < 8; k++) {
            int d = lane * 8 + k;
            float y = (v[k] - mu) * rstd * gs[d] + bs[d];
            o[k] = (y > 0.f) ? y : (__expf(y) - 1.0f);
        }
        float4* op = (float4*)(out + ((size_t)b * N_ + iBase + rr) * 256);
        op[lane * 2]     = make_float4(o[0], o[1], o[2], o[3]);
        op[lane * 2 + 1] = make_float4(o[4], o[5], o[6], o[7]);
    }
}

// ---------------------------------------------------------------------------
extern "C" void kernel_launch(void* const* d_in, const int* in_sizes, int n_in,
                              void* d_out, int out_size) {
    (void)in_sizes; (void)n_in; (void)out_size;
    const float* x     = (const float*)d_in[0];
    const int*   adj   = (const int*)d_in[1];
    const int*   et    = (const int*)d_in[2];
    const float* W     = (const float*)d_in[3];
    const float* a1    = (const float*)d_in[4];
    const float* a2    = (const float*)d_in[5];
    const float* eemb  = (const float*)d_in[6];
    const float* gamma = (const float*)d_in[7];
    const float* beta  = (const float*)d_in[8];
    float* out = (float*)d_out;

    // K1: Wh = x @ W (2xTF32 split tensor cores) + fused s1/s2 scores
    {
        dim3 grid(OUTF_ / 128, (B_ * N_) / 64);
        gemm_score_kernel<<<grid, 256>>>(x, W, a1, a2);
    }
    // K2: fused attention (tensor cores) + LN + ELU
    {
        const int smemBytes = SMEM_FLOATS * 4;  // 109568
        cudaFuncSetAttribute(attn_kernel, cudaFuncAttributeMaxDynamicSharedMemorySize,
                             smemBytes);
        dim3 grid(N_ / IT_, B_);
        attn_kernel<<<grid, 512, smemBytes>>>(adj, et, eemb, gamma, beta, out);
    }
}